// round 1
// baseline (speedup 1.0000x reference)
#include <cuda_runtime.h>
#include <cuda_bf16.h>
#include <math.h>

// ---------------------------------------------------------------------------
// AvULoss: N=2097152 rows, C=32 logits each.
//   probs = softmax(logits); conf = max p = 1/S (S = sum exp(l - m));
//   pred  = argmax logits (first-max tie-break, matches jnp.argmax);
//   unc   = -sum p log(p+eps)  ==  log S - (sum e*d)/S   (d = l - m), eps negl.
//   t = tanh(unc); 4 masked sums -> avu -> -log(avu + eps).
// Memory-bound: 256MB logits + labels. One pass, block-reduce, double atomics.
// ---------------------------------------------------------------------------

__device__ double g_acc[4];
__device__ int    g_lab64;   // 1 if labels are stored as int64, 0 if int32

__global__ void avu_init(const int* __restrict__ labels32) {
    if (threadIdx.x == 0) {
        // Layout probe: labels are in [0,32). If the buffer is int64 (LE),
        // every odd int32 word of the first 64 words is 0. If int32, the odd
        // words are themselves random labels; all-zero is (1/32)^32 ~ 0, and
        // inputs are a fixed seed, so this is deterministic.
        int all_zero_odd = 1;
        #pragma unroll
        for (int i = 1; i < 64; i += 2) {
            if (labels32[i] != 0) { all_zero_odd = 0; }
        }
        g_lab64 = all_zero_odd;
        g_acc[0] = 0.0; g_acc[1] = 0.0; g_acc[2] = 0.0; g_acc[3] = 0.0;
    }
}

__global__ __launch_bounds__(256)
void avu_main(const float* __restrict__ logits,
              const int*   __restrict__ labels32,
              const float* __restrict__ unc_th_p,
              int N)
{
    const int row = blockIdx.x * 256 + threadIdx.x;
    float c0 = 0.f, c1 = 0.f, c2 = 0.f, c3 = 0.f;

    if (row < N) {
        const float4* p = reinterpret_cast<const float4*>(logits) + (size_t)row * 8;
        float f[32];
        #pragma unroll
        for (int i = 0; i < 8; i++) {
            float4 v = __ldg(p + i);
            f[4*i + 0] = v.x; f[4*i + 1] = v.y; f[4*i + 2] = v.z; f[4*i + 3] = v.w;
        }

        // max + first-occurrence argmax (strict > keeps first index)
        float m = f[0]; int am = 0;
        #pragma unroll
        for (int i = 1; i < 32; i++) {
            if (f[i] > m) { m = f[i]; am = i; }
        }

        // S = sum exp(d), dot = sum exp(d)*d  with d = l - m  (all d <= 0)
        float S = 0.f, dot = 0.f;
        #pragma unroll
        for (int i = 0; i < 32; i++) {
            float d = f[i] - m;
            float e = __expf(d);
            S   += e;
            dot  = __fmaf_rn(e, d, dot);
        }

        float conf = __fdividef(1.0f, S);          // max prob = exp(0)/S
        float unc  = __logf(S) - dot * conf;       // predictive entropy
        float t;
        asm("tanh.approx.f32 %0, %1;" : "=f"(t) : "f"(unc));

        int lab = g_lab64 ? labels32[2 * row] : labels32[row];
        bool accurate = (lab == am);
        bool certain  = (unc <= unc_th_p[0]);

        float w  = 1.0f - t;
        float ic = 1.0f - conf;
        if (accurate) { if (certain) c0 = conf * w; else c1 = conf * t; }
        else          { if (certain) c2 = ic   * w; else c3 = ic   * t; }
    }

    // warp reduce (4 scalars)
    #pragma unroll
    for (int o = 16; o > 0; o >>= 1) {
        c0 += __shfl_down_sync(0xffffffffu, c0, o);
        c1 += __shfl_down_sync(0xffffffffu, c1, o);
        c2 += __shfl_down_sync(0xffffffffu, c2, o);
        c3 += __shfl_down_sync(0xffffffffu, c3, o);
    }

    __shared__ float sm[4][8];
    int wid = threadIdx.x >> 5;
    int lid = threadIdx.x & 31;
    if (lid == 0) { sm[0][wid] = c0; sm[1][wid] = c1; sm[2][wid] = c2; sm[3][wid] = c3; }
    __syncthreads();

    if (threadIdx.x < 4) {
        float s = 0.f;
        #pragma unroll
        for (int i = 0; i < 8; i++) s += sm[threadIdx.x][i];
        atomicAdd(&g_acc[threadIdx.x], (double)s);   // RED.F64, result unused
    }
}

__global__ void avu_finish(float* __restrict__ out) {
    double a0 = g_acc[0], a1 = g_acc[1], a2 = g_acc[2], a3 = g_acc[3];
    double avu = (a0 + a3) / (a0 + a1 + a2 + a3 + 1e-10);
    out[0] = (float)(-log(avu + 1e-10));
}

extern "C" void kernel_launch(void* const* d_in, const int* in_sizes, int n_in,
                              void* d_out, int out_size)
{
    const float* logits = (const float*)d_in[0];
    const int*   labels = (const int*)  d_in[1];   // int32 or int64 (probed)
    const float* unc_th = (const float*)d_in[2];
    const int N = in_sizes[1];                      // number of rows

    avu_init<<<1, 32>>>(labels);
    avu_main<<<(N + 255) / 256, 256>>>(logits, labels, unc_th, N);
    avu_finish<<<1, 1>>>((float*)d_out);
}

// round 2
// speedup vs baseline: 1.1539x; 1.1539x over previous
#include <cuda_runtime.h>
#include <math.h>

// ---------------------------------------------------------------------------
// AvULoss fused single-kernel: N rows x C=32 logits.
//   conf = 1/S (S = sum exp(l-m)); pred = argmax (first-max);
//   unc  = log S - (sum e*d)/S ; t = tanh(unc);
//   4 masked sums -> avu -> -log(avu+eps).
// R2: coalesced gmem loads staged through swizzled shared (kills the 32-
//     wavefront-per-LDG pattern of R1), single fused kernel with last-block
//     finish + self-reset (graph-replay safe).
// ---------------------------------------------------------------------------

__device__ double       g_acc[4];
__device__ unsigned int g_done = 0;

__global__ __launch_bounds__(256)
void avu_fused(const float* __restrict__ logits,
               const int*   __restrict__ labels32,
               const float* __restrict__ unc_th_p,
               int N, float* __restrict__ out)
{
    __shared__ float sdata[256 * 32];   // 32KB: 256 rows x 32 f32, swizzled
    __shared__ int   s_lab64;
    const int t   = threadIdx.x;
    const int bid = blockIdx.x;

    // Label layout probe (int64 vs int32 storage): labels < 32, so int64 (LE)
    // => odd int32 words of the first 64 words are all zero. Deterministic
    // for fixed-seed inputs; (1/32)^32 false-positive for int32.
    if (t == 0) {
        int all_zero_odd = 1;
        #pragma unroll
        for (int i = 1; i < 64; i += 2)
            if (labels32[i] != 0) all_zero_odd = 0;
        s_lab64 = all_zero_odd;
    }

    // ---- Stage 256 rows, fully coalesced (lane-consecutive float4). ----
    // Shared layout: row r, col-group c (4 floats) stored at column group
    // c ^ (r & 7)  => per-row reads are quarter-warp conflict-free.
    const size_t base4  = (size_t)bid * 2048;       // float4 units
    const size_t total4 = (size_t)N * 8;
    const float4* gp = reinterpret_cast<const float4*>(logits) + base4;
    #pragma unroll
    for (int i = 0; i < 8; i++) {
        int g = i * 256 + t;
        float4 v = make_float4(0.f, 0.f, 0.f, 0.f);
        if (base4 + (size_t)g < total4) v = gp[g];
        int r = g >> 3, c = g & 7;
        *reinterpret_cast<float4*>(&sdata[r * 32 + ((c ^ (r & 7)) << 2)]) = v;
    }
    __syncthreads();

    // ---- Per-row softmax stats ----
    const int row = bid * 256 + t;
    float c0 = 0.f, c1 = 0.f, c2 = 0.f, c3 = 0.f;
    if (row < N) {
        float f[32];
        #pragma unroll
        for (int i = 0; i < 8; i++) {
            float4 v = *reinterpret_cast<const float4*>(
                &sdata[t * 32 + ((i ^ (t & 7)) << 2)]);
            f[4*i+0] = v.x; f[4*i+1] = v.y; f[4*i+2] = v.z; f[4*i+3] = v.w;
        }

        float m = f[0]; int am = 0;
        #pragma unroll
        for (int i = 1; i < 32; i++)
            if (f[i] > m) { m = f[i]; am = i; }   // strict > = first-max

        float S = 0.f, dot = 0.f;
        #pragma unroll
        for (int i = 0; i < 32; i++) {
            float d = f[i] - m;
            float e = __expf(d);
            S   += e;
            dot  = __fmaf_rn(e, d, dot);
        }

        float conf = __fdividef(1.0f, S);
        float unc  = __logf(S) - dot * conf;
        float tn;
        asm("tanh.approx.f32 %0, %1;" : "=f"(tn) : "f"(unc));

        int  lab      = s_lab64 ? labels32[2 * row] : labels32[row];
        bool accurate = (lab == am);
        bool certain  = (unc <= unc_th_p[0]);

        float w = 1.0f - tn, ic = 1.0f - conf;
        if (accurate) { if (certain) c0 = conf * w; else c1 = conf * tn; }
        else          { if (certain) c2 = ic   * w; else c3 = ic   * tn; }
    }

    // ---- Block reduction (4 scalars) ----
    #pragma unroll
    for (int o = 16; o > 0; o >>= 1) {
        c0 += __shfl_down_sync(0xffffffffu, c0, o);
        c1 += __shfl_down_sync(0xffffffffu, c1, o);
        c2 += __shfl_down_sync(0xffffffffu, c2, o);
        c3 += __shfl_down_sync(0xffffffffu, c3, o);
    }
    __shared__ float smr[4][8];
    int wid = t >> 5, lid = t & 31;
    if (lid == 0) { smr[0][wid]=c0; smr[1][wid]=c1; smr[2][wid]=c2; smr[3][wid]=c3; }
    __syncthreads();
    if (t < 4) {
        float s = 0.f;
        #pragma unroll
        for (int i = 0; i < 8; i++) s += smr[t][i];
        atomicAdd(&g_acc[t], (double)s);
    }

    // ---- Last-block finish (threadfence-reduction pattern) ----
    __threadfence();
    __syncthreads();
    __shared__ unsigned int s_rank;
    if (t == 0) s_rank = atomicAdd(&g_done, 1u);
    __syncthreads();
    if (t == 0 && s_rank == gridDim.x - 1) {
        __threadfence();
        double a0 = atomicAdd(&g_acc[0], 0.0);
        double a1 = atomicAdd(&g_acc[1], 0.0);
        double a2 = atomicAdd(&g_acc[2], 0.0);
        double a3 = atomicAdd(&g_acc[3], 0.0);
        double avu = (a0 + a3) / (a0 + a1 + a2 + a3 + 1e-10);
        out[0] = (float)(-log(avu + 1e-10));
        // self-reset so every graph replay starts clean
        g_acc[0] = 0.0; g_acc[1] = 0.0; g_acc[2] = 0.0; g_acc[3] = 0.0;
        __threadfence();
        g_done = 0u;
    }
}

extern "C" void kernel_launch(void* const* d_in, const int* in_sizes, int n_in,
                              void* d_out, int out_size)
{
    const float* logits = (const float*)d_in[0];
    const int*   labels = (const int*)  d_in[1];   // int32 or int64 (probed)
    const float* unc_th = (const float*)d_in[2];
    const int N = in_sizes[1];                      // rows

    avu_fused<<<(N + 255) / 256, 256>>>(logits, labels, unc_th, N, (float*)d_out);
}

// round 3
// speedup vs baseline: 1.2300x; 1.0659x over previous
#include <cuda_runtime.h>
#include <math.h>

// ---------------------------------------------------------------------------
// AvULoss fused: N rows x C=32. R3: argmax -> (f[label]==max) via FMNMX tree,
// packed f32x2 arithmetic (FFMA2/ADD2) for d/S/dot, log2-space entropy.
// ---------------------------------------------------------------------------

__device__ double       g_acc[4];
__device__ unsigned int g_done = 0;

#define LOG2E 1.4426950408889634f
#define LN2   0.6931471805599453f

__device__ __forceinline__ unsigned long long pk2(float lo, float hi) {
    unsigned long long r;
    asm("mov.b64 %0, {%1,%2};" : "=l"(r) : "f"(lo), "f"(hi));
    return r;
}
__device__ __forceinline__ void upk2(unsigned long long v, float& lo, float& hi) {
    asm("mov.b64 {%0,%1}, %2;" : "=f"(lo), "=f"(hi) : "l"(v));
}
__device__ __forceinline__ unsigned long long fma2(unsigned long long a,
                                                   unsigned long long b,
                                                   unsigned long long c) {
    unsigned long long r;
    asm("fma.rn.f32x2 %0, %1, %2, %3;" : "=l"(r) : "l"(a), "l"(b), "l"(c));
    return r;
}
__device__ __forceinline__ unsigned long long add2(unsigned long long a,
                                                   unsigned long long b) {
    unsigned long long r;
    asm("add.rn.f32x2 %0, %1, %2;" : "=l"(r) : "l"(a), "l"(b));
    return r;
}
__device__ __forceinline__ float ex2f(float x) {
    float r; asm("ex2.approx.f32 %0, %1;" : "=f"(r) : "f"(x)); return r;
}
__device__ __forceinline__ float lg2f(float x) {
    float r; asm("lg2.approx.f32 %0, %1;" : "=f"(r) : "f"(x)); return r;
}
__device__ __forceinline__ float rcpf(float x) {
    float r; asm("rcp.approx.f32 %0, %1;" : "=f"(r) : "f"(x)); return r;
}
__device__ __forceinline__ float tanhf_hw(float x) {
    float r; asm("tanh.approx.f32 %0, %1;" : "=f"(r) : "f"(x)); return r;
}

__global__ __launch_bounds__(256)
void avu_fused(const float* __restrict__ logits,
               const int*   __restrict__ labels32,
               const float* __restrict__ unc_th_p,
               int N, float* __restrict__ out)
{
    __shared__ float sdata[256 * 32];   // 32KB swizzled tile
    __shared__ int   s_lab64;
    __shared__ float s_th;
    const int t   = threadIdx.x;
    const int bid = blockIdx.x;

    if (t == 0) {
        // int64-vs-int32 label storage probe (labels < 32 => odd LE words 0)
        int all_zero_odd = 1;
        #pragma unroll
        for (int i = 1; i < 64; i += 2)
            if (labels32[i] != 0) all_zero_odd = 0;
        s_lab64 = all_zero_odd;
        s_th    = unc_th_p[0];
    }

    // ---- Stage 256 rows coalesced; swizzle col-group by (row & 7). ----
    const size_t base4  = (size_t)bid * 2048;
    const size_t total4 = (size_t)N * 8;
    const float4* gp = reinterpret_cast<const float4*>(logits) + base4;
    #pragma unroll
    for (int i = 0; i < 8; i++) {
        int g = i * 256 + t;
        float4 v = make_float4(0.f, 0.f, 0.f, 0.f);
        if (base4 + (size_t)g < total4) v = gp[g];
        int r = g >> 3, c = g & 7;
        *reinterpret_cast<float4*>(&sdata[r * 32 + ((c ^ (r & 7)) << 2)]) = v;
    }

    // label load overlaps staging latency
    const int row = bid * 256 + t;
    int lab = 0;
    if (row < N) {
        // (s_lab64 not ready yet; load both safely via arithmetic after sync)
    }
    __syncthreads();
    if (row < N) lab = s_lab64 ? labels32[2 * row] : labels32[row];

    float c0 = 0.f, c1 = 0.f, c2 = 0.f, c3 = 0.f;
    if (row < N) {
        float f[32];
        #pragma unroll
        for (int i = 0; i < 8; i++) {
            float4 v = *reinterpret_cast<const float4*>(
                &sdata[t * 32 + ((i ^ (t & 7)) << 2)]);
            f[4*i+0] = v.x; f[4*i+1] = v.y; f[4*i+2] = v.z; f[4*i+3] = v.w;
        }

        // max via FMNMX tree (31 ops)
        float mx[16];
        #pragma unroll
        for (int i = 0; i < 16; i++) mx[i] = fmaxf(f[2*i], f[2*i+1]);
        #pragma unroll
        for (int s = 8; s > 0; s >>= 1)
            #pragma unroll
            for (int i = 0; i < 16; i++)      // only first s iterations matter
                if (i < s) mx[i] = fmaxf(mx[i], mx[i + s]);
        float m = mx[0];

        // packed: d2 = (f - m)*log2e ; e = 2^d2 ; S += e ; dot2 += e*d2
        const unsigned long long L2E2 = pk2(LOG2E, LOG2E);
        float nm = -m * LOG2E;
        const unsigned long long NM2 = pk2(nm, nm);
        unsigned long long S2   = 0ull;      // (0.f, 0.f)
        unsigned long long D2ac = 0ull;
        #pragma unroll
        for (int i = 0; i < 16; i++) {
            unsigned long long fp = pk2(f[2*i], f[2*i+1]);
            unsigned long long d2 = fma2(fp, L2E2, NM2);
            float dlo, dhi; upk2(d2, dlo, dhi);
            unsigned long long e2 = pk2(ex2f(dlo), ex2f(dhi));
            S2   = add2(S2, e2);
            D2ac = fma2(e2, d2, D2ac);
        }
        float sl, sh, dl, dh;
        upk2(S2, sl, sh); upk2(D2ac, dl, dh);
        float S    = sl + sh;
        float dot2 = dl + dh;

        float conf = rcpf(S);                       // 1/S = max prob
        float unc  = LN2 * (lg2f(S) - dot2 * conf); // predictive entropy
        float tn   = tanhf_hw(unc);

        // accurate: label attains the max (ties measure-zero)
        float fl = sdata[t * 32 + ((((lab >> 2) ^ (t & 7)) << 2) | (lab & 3))];
        bool accurate = (fl == m);
        bool certain  = (unc <= s_th);

        float w = 1.0f - tn, ic = 1.0f - conf;
        if (accurate) { if (certain) c0 = conf * w; else c1 = conf * tn; }
        else          { if (certain) c2 = ic   * w; else c3 = ic   * tn; }
    }

    // ---- Block reduction ----
    #pragma unroll
    for (int o = 16; o > 0; o >>= 1) {
        c0 += __shfl_down_sync(0xffffffffu, c0, o);
        c1 += __shfl_down_sync(0xffffffffu, c1, o);
        c2 += __shfl_down_sync(0xffffffffu, c2, o);
        c3 += __shfl_down_sync(0xffffffffu, c3, o);
    }
    __shared__ float smr[4][8];
    int wid = t >> 5, lid = t & 31;
    if (lid == 0) { smr[0][wid]=c0; smr[1][wid]=c1; smr[2][wid]=c2; smr[3][wid]=c3; }
    __syncthreads();
    if (t < 4) {
        float s = 0.f;
        #pragma unroll
        for (int i = 0; i < 8; i++) s += smr[t][i];
        atomicAdd(&g_acc[t], (double)s);
    }

    // ---- Last-block finish + self-reset (graph-replay safe) ----
    __threadfence();
    __syncthreads();
    __shared__ unsigned int s_rank;
    if (t == 0) s_rank = atomicAdd(&g_done, 1u);
    __syncthreads();
    if (t == 0 && s_rank == gridDim.x - 1) {
        __threadfence();
        double a0 = atomicAdd(&g_acc[0], 0.0);
        double a1 = atomicAdd(&g_acc[1], 0.0);
        double a2 = atomicAdd(&g_acc[2], 0.0);
        double a3 = atomicAdd(&g_acc[3], 0.0);
        double avu = (a0 + a3) / (a0 + a1 + a2 + a3 + 1e-10);
        out[0] = (float)(-log(avu + 1e-10));
        g_acc[0] = 0.0; g_acc[1] = 0.0; g_acc[2] = 0.0; g_acc[3] = 0.0;
        __threadfence();
        g_done = 0u;
    }
}

extern "C" void kernel_launch(void* const* d_in, const int* in_sizes, int n_in,
                              void* d_out, int out_size)
{
    const float* logits = (const float*)d_in[0];
    const int*   labels = (const int*)  d_in[1];
    const float* unc_th = (const float*)d_in[2];
    const int N = in_sizes[1];

    avu_fused<<<(N + 255) / 256, 256>>>(logits, labels, unc_th, N, (float*)d_out);
}

// round 5
// speedup vs baseline: 1.3599x; 1.1056x over previous
#include <cuda_runtime.h>
#include <math.h>

// ---------------------------------------------------------------------------
// AvULoss fused, R5 (= R4 with redux.sync.f32 removed; unsupported on sm_103):
// cp.async staging, 128-thread blocks (16KB tile), 2-term num/den reduction
// via butterfly shuffles.
// ---------------------------------------------------------------------------

__device__ double       g_acc[2];
__device__ unsigned int g_done = 0;

#define LOG2E 1.4426950408889634f
#define LN2   0.6931471805599453f

__device__ __forceinline__ unsigned long long pk2(float lo, float hi) {
    unsigned long long r;
    asm("mov.b64 %0, {%1,%2};" : "=l"(r) : "f"(lo), "f"(hi));
    return r;
}
__device__ __forceinline__ void upk2(unsigned long long v, float& lo, float& hi) {
    asm("mov.b64 {%0,%1}, %2;" : "=f"(lo), "=f"(hi) : "l"(v));
}
__device__ __forceinline__ unsigned long long fma2(unsigned long long a,
                                                   unsigned long long b,
                                                   unsigned long long c) {
    unsigned long long r;
    asm("fma.rn.f32x2 %0, %1, %2, %3;" : "=l"(r) : "l"(a), "l"(b), "l"(c));
    return r;
}
__device__ __forceinline__ unsigned long long add2(unsigned long long a,
                                                   unsigned long long b) {
    unsigned long long r;
    asm("add.rn.f32x2 %0, %1, %2;" : "=l"(r) : "l"(a), "l"(b));
    return r;
}
__device__ __forceinline__ float ex2f(float x) {
    float r; asm("ex2.approx.f32 %0, %1;" : "=f"(r) : "f"(x)); return r;
}
__device__ __forceinline__ float lg2f(float x) {
    float r; asm("lg2.approx.f32 %0, %1;" : "=f"(r) : "f"(x)); return r;
}
__device__ __forceinline__ float rcpf(float x) {
    float r; asm("rcp.approx.f32 %0, %1;" : "=f"(r) : "f"(x)); return r;
}
__device__ __forceinline__ float tanhf_hw(float x) {
    float r; asm("tanh.approx.f32 %0, %1;" : "=f"(r) : "f"(x)); return r;
}
__device__ __forceinline__ unsigned int smem_u32(const void* p) {
    unsigned int a;
    asm("{ .reg .u64 t; cvta.to.shared.u64 t, %1; cvt.u32.u64 %0, t; }"
        : "=r"(a) : "l"(p));
    return a;
}

__global__ __launch_bounds__(128)
void avu_fused(const float* __restrict__ logits,
               const int*   __restrict__ labels32,
               const float* __restrict__ unc_th_p,
               int N, float* __restrict__ out)
{
    __shared__ float sdata[128 * 32];   // 16KB swizzled tile
    __shared__ float smr[2][4];
    __shared__ int   s_lab64;
    __shared__ float s_th;
    __shared__ unsigned int s_rank;
    const int t   = threadIdx.x;
    const int bid = blockIdx.x;

    if (t == 0) {
        // int64-vs-int32 label storage probe (labels < 32 => odd LE words 0)
        int all_zero_odd = 1;
        #pragma unroll
        for (int i = 1; i < 64; i += 2)
            if (labels32[i] != 0) all_zero_odd = 0;
        s_lab64 = all_zero_odd;
        s_th    = unc_th_p[0];
    }

    // ---- Stage 128 rows via cp.async; col-group swizzled by (row & 7). ----
    const size_t base4  = (size_t)bid * 1024;       // float4 units
    const size_t total4 = (size_t)N * 8;
    const float4* gp = reinterpret_cast<const float4*>(logits) + base4;
    const unsigned int sbase = smem_u32(sdata);
    #pragma unroll
    for (int i = 0; i < 8; i++) {
        int g = i * 128 + t;
        if (base4 + (size_t)g < total4) {
            int r = g >> 3, c = g & 7;
            unsigned int dst = sbase + ((r * 32 + ((c ^ (r & 7)) << 2)) << 2);
            asm volatile("cp.async.cg.shared.global [%0], [%1], 16;"
                         :: "r"(dst), "l"(gp + g) : "memory");
        }
    }
    asm volatile("cp.async.commit_group;" ::: "memory");
    asm volatile("cp.async.wait_group 0;" ::: "memory");
    __syncthreads();

    const int row = bid * 128 + t;
    float c_num = 0.f, c_den = 0.f;
    if (row < N) {
        int lab = s_lab64 ? labels32[2 * row] : labels32[row];

        float f[32];
        #pragma unroll
        for (int i = 0; i < 8; i++) {
            float4 v = *reinterpret_cast<const float4*>(
                &sdata[t * 32 + ((i ^ (t & 7)) << 2)]);
            f[4*i+0] = v.x; f[4*i+1] = v.y; f[4*i+2] = v.z; f[4*i+3] = v.w;
        }

        // max via FMNMX tree (31 ops)
        float mx[16];
        #pragma unroll
        for (int i = 0; i < 16; i++) mx[i] = fmaxf(f[2*i], f[2*i+1]);
        #pragma unroll
        for (int s = 8; s > 0; s >>= 1)
            #pragma unroll
            for (int i = 0; i < 16; i++)
                if (i < s) mx[i] = fmaxf(mx[i], mx[i + s]);
        const float m = mx[0];

        // packed: d2 = (f-m)*log2e ; e = 2^d2 ; S += e ; dot2 += e*d2
        const unsigned long long L2E2 = pk2(LOG2E, LOG2E);
        const float nm = -m * LOG2E;
        const unsigned long long NM2 = pk2(nm, nm);
        unsigned long long S2 = 0ull, D2 = 0ull;
        #pragma unroll
        for (int i = 0; i < 16; i++) {
            unsigned long long fp = pk2(f[2*i], f[2*i+1]);
            unsigned long long d2 = fma2(fp, L2E2, NM2);
            float dlo, dhi; upk2(d2, dlo, dhi);
            unsigned long long e2 = pk2(ex2f(dlo), ex2f(dhi));
            S2 = add2(S2, e2);
            D2 = fma2(e2, d2, D2);
        }
        float sl, sh, dl, dh;
        upk2(S2, sl, sh); upk2(D2, dl, dh);
        const float S    = sl + sh;
        const float dot2 = dl + dh;

        const float conf = rcpf(S);                       // max prob = 1/S
        const float unc  = LN2 * (lg2f(S) - dot2 * conf); // entropy
        const float tn   = tanhf_hw(unc);

        const float fl = sdata[t * 32 + ((((lab >> 2) ^ (t & 7)) << 2) | (lab & 3))];
        const bool accurate = (fl == m);                  // ties measure-zero
        const bool certain  = (unc <= s_th);

        c_den = (accurate ? conf : 1.0f - conf) * (certain ? 1.0f - tn : tn);
        c_num = (accurate == certain) ? c_den : 0.f;      // AC + IU
    }

    // ---- Warp reduction: butterfly over both scalars ----
    #pragma unroll
    for (int o = 16; o > 0; o >>= 1) {
        c_num += __shfl_xor_sync(0xffffffffu, c_num, o);
        c_den += __shfl_xor_sync(0xffffffffu, c_den, o);
    }
    const int wid = t >> 5, lid = t & 31;
    if (lid == 0) { smr[0][wid] = c_num; smr[1][wid] = c_den; }
    __syncthreads();
    if (t < 2) {
        float s = smr[t][0] + smr[t][1] + smr[t][2] + smr[t][3];
        atomicAdd(&g_acc[t], (double)s);
    }

    // ---- Last-block finish + self-reset (graph-replay safe) ----
    __threadfence();
    __syncthreads();
    if (t == 0) s_rank = atomicAdd(&g_done, 1u);
    __syncthreads();
    if (t == 0 && s_rank == gridDim.x - 1) {
        __threadfence();
        double num = atomicAdd(&g_acc[0], 0.0);
        double den = atomicAdd(&g_acc[1], 0.0);
        double avu = num / (den + 1e-10);
        out[0] = (float)(-log(avu + 1e-10));
        g_acc[0] = 0.0; g_acc[1] = 0.0;
        __threadfence();
        g_done = 0u;
    }
}

extern "C" void kernel_launch(void* const* d_in, const int* in_sizes, int n_in,
                              void* d_out, int out_size)
{
    const float* logits = (const float*)d_in[0];
    const int*   labels = (const int*)  d_in[1];
    const float* unc_th = (const float*)d_in[2];
    const int N = in_sizes[1];

    avu_fused<<<(N + 127) / 128, 128>>>(logits, labels, unc_th, N, (float*)d_out);
}